// round 3
// baseline (speedup 1.0000x reference)
#include <cuda_runtime.h>

#define N_NODES 40000
#define N_EDGES 640000
#define IN_F    128
#define HID     256
#define CLS     40
#define ROW4    (IN_F/4)   // 32 float4 per row

// ---- scratch (__device__ globals; no allocations allowed) ----
__device__ int    g_deg[N_NODES];
__device__ int    g_rowptr[N_NODES + 1];
__device__ int    g_cursor[N_NODES];
__device__ int    g_csr[N_EDGES];
__device__ float  g_norm[N_NODES];
__device__ float4 g_bufA[N_NODES * ROW4];   // 20.48 MB
__device__ float4 g_bufB[N_NODES * ROW4];   // 20.48 MB
__device__ float  g_z[N_NODES * HID];       // 40.96 MB

// ---------------- degree ----------------
__global__ void k_zero() {
    int i = blockIdx.x * blockDim.x + threadIdx.x;
    if (i < N_NODES) g_deg[i] = 0;
}

__global__ void k_deg(const int* __restrict__ dst) {
    int e = blockIdx.x * blockDim.x + threadIdx.x;
    if (e < N_EDGES) atomicAdd(&g_deg[dst[e]], 1);
}

// ---------------- exclusive scan (single block, 1024 threads) ----------------
__global__ void k_scan() {
    __shared__ int part[1024];
    const int t = threadIdx.x;
    const int C = 40;                       // 1024*40 = 40960 >= 40001
    int base = t * C;
    int s = 0;
    for (int i = 0; i < C; i++) {
        int idx = base + i;
        if (idx < N_NODES) s += g_deg[idx];
    }
    part[t] = s;
    __syncthreads();
    for (int o = 1; o < 1024; o <<= 1) {
        int v = (t >= o) ? part[t - o] : 0;
        __syncthreads();
        part[t] += v;
        __syncthreads();
    }
    int pre = (t == 0) ? 0 : part[t - 1];
    for (int i = 0; i < C; i++) {
        int idx = base + i;
        if (idx <= N_NODES) {
            g_rowptr[idx] = pre;
            if (idx < N_NODES) {
                g_cursor[idx] = pre;
                pre += g_deg[idx];
            }
        }
    }
}

// ---------------- CSR fill (atomic cursor; order fixed up by sort) ----------------
__global__ void k_fill(const int* __restrict__ src, const int* __restrict__ dst) {
    int e = blockIdx.x * blockDim.x + threadIdx.x;
    if (e < N_EDGES) {
        int d = dst[e];
        int pos = atomicAdd(&g_cursor[d], 1);
        g_csr[pos] = src[e];
    }
}

// ---------------- per-node insertion sort (determinism: fixed sum order) ----------------
__global__ void k_sort() {
    int n = blockIdx.x * blockDim.x + threadIdx.x;
    if (n < N_NODES) {
        int b = g_rowptr[n], e = g_rowptr[n + 1];
        for (int i = b + 1; i < e; i++) {
            int v = g_csr[i];
            int j = i - 1;
            while (j >= b && g_csr[j] > v) { g_csr[j + 1] = g_csr[j]; j--; }
            g_csr[j + 1] = v;
        }
    }
}

__global__ void k_norm() {
    int i = blockIdx.x * blockDim.x + threadIdx.x;
    if (i < N_NODES) g_norm[i] = rsqrtf(fmaxf((float)g_deg[i], 1.0f));
}

// ---------------- bufA = features * norm ----------------
__global__ void k_scale_init(const float4* __restrict__ feat) {
    int t = blockIdx.x * blockDim.x + threadIdx.x;
    if (t < N_NODES * ROW4) {
        float n = g_norm[t >> 5];
        float4 v = feat[t];
        v.x *= n; v.y *= n; v.z *= n; v.w *= n;
        g_bufA[t] = v;
    }
}

// ---------------- gather hop ----------------
// dir=0: in=g_bufA, out=g_bufB (hop 1, pw=2: post-norm * next-pre-norm folded)
// dir=1: in=g_bufB, out=g_bufA (hop 2, pw=1: final post-norm)
// Buffers resolved in DEVICE code (host must never take __device__ symbol addresses).
// One warp per dst node; lane j owns float4 slice j of the 128-float row.
__global__ __launch_bounds__(256)
void k_gather(int dir, int pw) {
    const float4* __restrict__ in  = dir ? g_bufB : g_bufA;
    float4* __restrict__       out = dir ? g_bufA : g_bufB;

    int gt = blockIdx.x * blockDim.x + threadIdx.x;
    int w = gt >> 5;            // node id (grid sized exactly: w < N_NODES)
    int lane = gt & 31;
    int beg = g_rowptr[w], end = g_rowptr[w + 1];
    float4 acc = make_float4(0.f, 0.f, 0.f, 0.f);
    for (int base = beg; base < end; base += 32) {
        int cnt = min(32, end - base);
        int s_l = (base + lane < end) ? g_csr[base + lane] : 0;
        int k = 0;
        for (; k + 4 <= cnt; k += 4) {
            int s0 = __shfl_sync(0xffffffffu, s_l, k);
            int s1 = __shfl_sync(0xffffffffu, s_l, k + 1);
            int s2 = __shfl_sync(0xffffffffu, s_l, k + 2);
            int s3 = __shfl_sync(0xffffffffu, s_l, k + 3);
            float4 v0 = in[s0 * ROW4 + lane];
            float4 v1 = in[s1 * ROW4 + lane];
            float4 v2 = in[s2 * ROW4 + lane];
            float4 v3 = in[s3 * ROW4 + lane];
            acc.x += v0.x; acc.y += v0.y; acc.z += v0.z; acc.w += v0.w;
            acc.x += v1.x; acc.y += v1.y; acc.z += v1.z; acc.w += v1.w;
            acc.x += v2.x; acc.y += v2.y; acc.z += v2.z; acc.w += v2.w;
            acc.x += v3.x; acc.y += v3.y; acc.z += v3.z; acc.w += v3.w;
        }
        for (; k < cnt; k++) {
            int s = __shfl_sync(0xffffffffu, s_l, k);
            float4 v = in[s * ROW4 + lane];
            acc.x += v.x; acc.y += v.y; acc.z += v.z; acc.w += v.w;
        }
    }
    float nn = g_norm[w];
    float sc = (pw == 2) ? nn * nn : nn;
    acc.x *= sc; acc.y *= sc; acc.z *= sc; acc.w *= sc;
    out[w * ROW4 + lane] = acc;
}

// ---------------- GEMM1: z = relu(h @ W1 + b1), h = g_bufA ----------------
// CTA: 32 rows x 256 threads. Thread (ty,tx) computes z[ty*4+r][tx*8+j].
#define TM1 32
__global__ __launch_bounds__(256)
void k_gemm1(const float4* __restrict__ W1v, const float* __restrict__ b1) {
    __shared__ float sh[TM1][IN_F];     // 16 KB
    __shared__ float sw[16][HID];       // 16 KB  (k-tile of W1)

    const int t  = threadIdx.x;
    const int tx = t & 31;
    const int ty = t >> 5;
    const int row0 = blockIdx.x * TM1;

    const float4* hv = g_bufA + row0 * ROW4;
    float4* sh4 = reinterpret_cast<float4*>(&sh[0][0]);
    #pragma unroll
    for (int i = 0; i < 4; i++) sh4[t + i * 256] = hv[t + i * 256];

    float acc[4][8];
    #pragma unroll
    for (int r = 0; r < 4; r++)
        #pragma unroll
        for (int j = 0; j < 8; j++) acc[r][j] = 0.f;

    #pragma unroll 1
    for (int kt = 0; kt < 8; kt++) {
        __syncthreads();
        float4* sw4 = reinterpret_cast<float4*>(&sw[0][0]);
        const float4* w1t = W1v + kt * 16 * (HID / 4);   // 16 rows = 1024 float4
        #pragma unroll
        for (int i = 0; i < 4; i++) sw4[t + i * 256] = w1t[t + i * 256];
        __syncthreads();

        #pragma unroll
        for (int kk = 0; kk < 16; kk++) {
            float a0 = sh[ty * 4 + 0][kt * 16 + kk];
            float a1 = sh[ty * 4 + 1][kt * 16 + kk];
            float a2 = sh[ty * 4 + 2][kt * 16 + kk];
            float a3 = sh[ty * 4 + 3][kt * 16 + kk];
            float4 w0 = *reinterpret_cast<const float4*>(&sw[kk][tx * 8]);
            float4 w1 = *reinterpret_cast<const float4*>(&sw[kk][tx * 8 + 4]);
            float wb[8] = {w0.x, w0.y, w0.z, w0.w, w1.x, w1.y, w1.z, w1.w};
            #pragma unroll
            for (int j = 0; j < 8; j++) {
                acc[0][j] += a0 * wb[j];
                acc[1][j] += a1 * wb[j];
                acc[2][j] += a2 * wb[j];
                acc[3][j] += a3 * wb[j];
            }
        }
    }

    float bb[8];
    #pragma unroll
    for (int j = 0; j < 8; j++) bb[j] = b1[tx * 8 + j];

    float4* z4 = reinterpret_cast<float4*>(g_z);
    #pragma unroll
    for (int r = 0; r < 4; r++) {
        int row = row0 + ty * 4 + r;
        float4 z0, z1;
        z0.x = fmaxf(acc[r][0] + bb[0], 0.f);
        z0.y = fmaxf(acc[r][1] + bb[1], 0.f);
        z0.z = fmaxf(acc[r][2] + bb[2], 0.f);
        z0.w = fmaxf(acc[r][3] + bb[3], 0.f);
        z1.x = fmaxf(acc[r][4] + bb[4], 0.f);
        z1.y = fmaxf(acc[r][5] + bb[5], 0.f);
        z1.z = fmaxf(acc[r][6] + bb[6], 0.f);
        z1.w = fmaxf(acc[r][7] + bb[7], 0.f);
        z4[row * (HID / 4) + tx * 2]     = z0;
        z4[row * (HID / 4) + tx * 2 + 1] = z1;
    }
}

// ---------------- GEMM2: out = z @ W2 + b2 ----------------
// One warp per row; lane owns z[k] for k = lane*8..lane*8+7; shuffle-reduce per column.
__global__ __launch_bounds__(256)
void k_gemm2(const float* __restrict__ W2, const float* __restrict__ b2,
             float* __restrict__ out) {
    __shared__ float sW2T[CLS][HID];    // 40 KB
    __shared__ float sb2[CLS];

    const int t = threadIdx.x;
    for (int i = t; i < HID * CLS; i += 256) {
        int k = i / CLS, c = i - k * CLS;
        sW2T[c][k] = W2[i];
    }
    if (t < CLS) sb2[t] = b2[t];
    __syncthreads();

    const int row  = blockIdx.x * 8 + (t >> 5);   // grid sized exactly
    const int lane = t & 31;

    const float4* z4 = reinterpret_cast<const float4*>(g_z);
    float4 za = z4[row * (HID / 4) + lane * 2];
    float4 zb = z4[row * (HID / 4) + lane * 2 + 1];
    float zv[8] = {za.x, za.y, za.z, za.w, zb.x, zb.y, zb.z, zb.w};

    #pragma unroll 1
    for (int c0 = 0; c0 < CLS; c0 += 4) {
        float p[4];
        #pragma unroll
        for (int q = 0; q < 4; q++) {
            const float4* wp = reinterpret_cast<const float4*>(&sW2T[c0 + q][lane * 8]);
            float4 w0 = wp[0], w1 = wp[1];
            float s = zv[0] * w0.x;
            s += zv[1] * w0.y; s += zv[2] * w0.z; s += zv[3] * w0.w;
            s += zv[4] * w1.x; s += zv[5] * w1.y; s += zv[6] * w1.z; s += zv[7] * w1.w;
            p[q] = s;
        }
        #pragma unroll
        for (int o = 16; o > 0; o >>= 1) {
            p[0] += __shfl_xor_sync(0xffffffffu, p[0], o);
            p[1] += __shfl_xor_sync(0xffffffffu, p[1], o);
            p[2] += __shfl_xor_sync(0xffffffffu, p[2], o);
            p[3] += __shfl_xor_sync(0xffffffffu, p[3], o);
        }
        if (lane == 0) {
            out[row * CLS + c0 + 0] = p[0] + sb2[c0 + 0];
            out[row * CLS + c0 + 1] = p[1] + sb2[c0 + 1];
            out[row * CLS + c0 + 2] = p[2] + sb2[c0 + 2];
            out[row * CLS + c0 + 3] = p[3] + sb2[c0 + 3];
        }
    }
}

// ---------------- launch ----------------
extern "C" void kernel_launch(void* const* d_in, const int* in_sizes, int n_in,
                              void* d_out, int out_size) {
    const float* features = (const float*)d_in[0];
    const int*   src      = (const int*)d_in[1];
    const int*   dst      = (const int*)d_in[2];
    const float* W1       = (const float*)d_in[3];
    const float* b1       = (const float*)d_in[4];
    const float* W2       = (const float*)d_in[5];
    const float* b2       = (const float*)d_in[6];
    float* out = (float*)d_out;

    const int nodeBlocks = (N_NODES + 255) / 256;            // 157
    const int edgeBlocks = (N_EDGES + 255) / 256;            // 2500
    const int featBlocks = (N_NODES * ROW4 + 255) / 256;     // 5000
    const int warpBlocks = N_NODES * 32 / 256;               // 5000 (exact)

    k_zero<<<nodeBlocks, 256>>>();
    k_deg<<<edgeBlocks, 256>>>(dst);
    k_scan<<<1, 1024>>>();
    k_fill<<<edgeBlocks, 256>>>(src, dst);
    k_sort<<<nodeBlocks, 256>>>();
    k_norm<<<nodeBlocks, 256>>>();

    k_scale_init<<<featBlocks, 256>>>((const float4*)features);
    k_gather<<<warpBlocks, 256>>>(/*dir=*/0, /*pw=*/2);      // hop 1 (+ mid norm^2)
    k_gather<<<warpBlocks, 256>>>(/*dir=*/1, /*pw=*/1);      // hop 2 (+ final norm)

    k_gemm1<<<N_NODES / TM1, 256>>>((const float4*)W1, b1);
    k_gemm2<<<N_NODES / 8, 256>>>(W2, b2, out);
}

// round 4
// speedup vs baseline: 1.9192x; 1.9192x over previous
#include <cuda_runtime.h>

#define N_NODES 40000
#define N_EDGES 640000
#define IN_F    128
#define HID     256
#define CLS     40
#define ROW4    (IN_F/4)   // 32 float4 per row

typedef unsigned long long ull;

// packed f32x2 helpers (sm_103a)
#define FMA2(d, a, b)    asm("fma.rn.f32x2 %0, %1, %2, %3;" : "=l"(d) : "l"(a), "l"(b), "l"(d))
#define PACKDUP(d, f)    asm("mov.b64 %0, {%1, %1};" : "=l"(d) : "f"(f))
#define PACK2(d, lo, hi) asm("mov.b64 %0, {%1, %2};" : "=l"(d) : "f"(lo), "f"(hi))
#define UNPACK2(lo, hi, s) asm("mov.b64 {%0, %1}, %2;" : "=f"(lo), "=f"(hi) : "l"(s))

// ---- scratch (__device__ globals; no allocations allowed) ----
__device__ int    g_deg[N_NODES];
__device__ int    g_rowptr[N_NODES + 1];
__device__ int    g_cursor[N_NODES];
__device__ int    g_csr[N_EDGES];
__device__ float  g_norm[N_NODES];
__device__ float4 g_bufA[N_NODES * ROW4];   // 20.48 MB (hop2 out = MLP in)
__device__ float4 g_bufB[N_NODES * ROW4];   // 20.48 MB (hop1 out)

// ---------------- degree ----------------
__global__ void k_zero() {
    int i = blockIdx.x * blockDim.x + threadIdx.x;
    if (i < N_NODES) g_deg[i] = 0;
}

__global__ void k_deg(const int* __restrict__ dst) {
    int e = blockIdx.x * blockDim.x + threadIdx.x;
    if (e < N_EDGES) atomicAdd(&g_deg[dst[e]], 1);
}

// ---------------- exclusive scan (single block, 1024 threads) ----------------
__global__ void k_scan() {
    __shared__ int part[1024];
    const int t = threadIdx.x;
    const int C = 40;                       // 1024*40 = 40960 >= 40001
    int base = t * C;
    int s = 0;
    for (int i = 0; i < C; i++) {
        int idx = base + i;
        if (idx < N_NODES) s += g_deg[idx];
    }
    part[t] = s;
    __syncthreads();
    for (int o = 1; o < 1024; o <<= 1) {
        int v = (t >= o) ? part[t - o] : 0;
        __syncthreads();
        part[t] += v;
        __syncthreads();
    }
    int pre = (t == 0) ? 0 : part[t - 1];
    for (int i = 0; i < C; i++) {
        int idx = base + i;
        if (idx <= N_NODES) {
            g_rowptr[idx] = pre;
            if (idx < N_NODES) {
                g_cursor[idx] = pre;
                pre += g_deg[idx];
            }
        }
    }
}

// ---------------- CSR fill (atomic cursor; order canonicalized by sort) --------
__global__ void k_fill(const int* __restrict__ src, const int* __restrict__ dst) {
    int e = blockIdx.x * blockDim.x + threadIdx.x;
    if (e < N_EDGES) {
        int d = dst[e];
        int pos = atomicAdd(&g_cursor[d], 1);
        g_csr[pos] = src[e];
    }
}

// ---------------- per-node sort: warp bitonic (d<=32), smem fallback ----------
__global__ __launch_bounds__(256)
void k_sort() {
    __shared__ int scratch[8][512];
    const int wi   = threadIdx.x >> 5;
    const int lane = threadIdx.x & 31;
    const int n = blockIdx.x * 8 + wi;          // grid = 5000 blocks exactly
    int b = g_rowptr[n], e = g_rowptr[n + 1];
    int d = e - b;
    if (d <= 1) return;
    if (d <= 32) {
        int v = (lane < d) ? g_csr[b + lane] : 0x7fffffff;
        #pragma unroll
        for (int k = 2; k <= 32; k <<= 1) {
            #pragma unroll
            for (int j = k >> 1; j > 0; j >>= 1) {
                int pv = __shfl_xor_sync(0xffffffffu, v, j);
                bool dir   = ((lane & k) == 0);
                bool lower = ((lane & j) == 0);
                v = ((lower == dir) ? min(v, pv) : max(v, pv));
            }
        }
        if (lane < d) g_csr[b + lane] = v;
    } else if (d <= 512) {
        int* s = scratch[wi];
        for (int i = lane; i < d; i += 32) s[i] = g_csr[b + i];
        __syncwarp();
        if (lane == 0) {
            for (int i = 1; i < d; i++) {
                int v = s[i], j = i - 1;
                while (j >= 0 && s[j] > v) { s[j + 1] = s[j]; j--; }
                s[j + 1] = v;
            }
        }
        __syncwarp();
        for (int i = lane; i < d; i += 32) g_csr[b + i] = s[i];
    } else {
        if (lane == 0) {   // unreachable for this graph; correctness safety net
            for (int i = b + 1; i < e; i++) {
                int v = g_csr[i], j = i - 1;
                while (j >= b && g_csr[j] > v) { g_csr[j + 1] = g_csr[j]; j--; }
                g_csr[j + 1] = v;
            }
        }
    }
}

__global__ void k_norm() {
    int i = blockIdx.x * blockDim.x + threadIdx.x;
    if (i < N_NODES) g_norm[i] = rsqrtf(fmaxf((float)g_deg[i], 1.0f));
}

// ---------------- hop 1: bufB[d] = norm[d]^2 * sum_s feat[s]*norm[s] ----------
// One warp per dst node; lane owns one float4 slice. Source norm fused in.
__global__ __launch_bounds__(256)
void k_gather1(const float4* __restrict__ feat) {
    int gt = blockIdx.x * blockDim.x + threadIdx.x;
    int w = gt >> 5, lane = gt & 31;
    int beg = g_rowptr[w], end = g_rowptr[w + 1];
    float4 acc = make_float4(0.f, 0.f, 0.f, 0.f);
    for (int base = beg; base < end; base += 32) {
        int cnt = min(32, end - base);
        int idx = base + lane;
        int   s_l = (idx < end) ? g_csr[idx] : 0;
        float n_l = g_norm[s_l];
        int k = 0;
        for (; k + 8 <= cnt; k += 8) {
            int   s[8]; float nn[8];
            #pragma unroll
            for (int i = 0; i < 8; i++) {
                s[i]  = __shfl_sync(0xffffffffu, s_l, k + i);
                nn[i] = __shfl_sync(0xffffffffu, n_l, k + i);
            }
            float4 v[8];
            #pragma unroll
            for (int i = 0; i < 8; i++) v[i] = feat[s[i] * ROW4 + lane];
            #pragma unroll
            for (int i = 0; i < 8; i++) {
                acc.x = fmaf(v[i].x, nn[i], acc.x);
                acc.y = fmaf(v[i].y, nn[i], acc.y);
                acc.z = fmaf(v[i].z, nn[i], acc.z);
                acc.w = fmaf(v[i].w, nn[i], acc.w);
            }
        }
        for (; k < cnt; k++) {
            int   s  = __shfl_sync(0xffffffffu, s_l, k);
            float nn = __shfl_sync(0xffffffffu, n_l, k);
            float4 v = feat[s * ROW4 + lane];
            acc.x = fmaf(v.x, nn, acc.x);
            acc.y = fmaf(v.y, nn, acc.y);
            acc.z = fmaf(v.z, nn, acc.z);
            acc.w = fmaf(v.w, nn, acc.w);
        }
    }
    float nn = g_norm[w];
    float sc = nn * nn;
    acc.x *= sc; acc.y *= sc; acc.z *= sc; acc.w *= sc;
    g_bufB[w * ROW4 + lane] = acc;
}

// ---------------- hop 2: bufA[d] = norm[d] * sum_s bufB[s] ----------
__global__ __launch_bounds__(256)
void k_gather2() {
    const float4* __restrict__ in = g_bufB;
    int gt = blockIdx.x * blockDim.x + threadIdx.x;
    int w = gt >> 5, lane = gt & 31;
    int beg = g_rowptr[w], end = g_rowptr[w + 1];
    float4 acc = make_float4(0.f, 0.f, 0.f, 0.f);
    for (int base = beg; base < end; base += 32) {
        int cnt = min(32, end - base);
        int idx = base + lane;
        int s_l = (idx < end) ? g_csr[idx] : 0;
        int k = 0;
        for (; k + 8 <= cnt; k += 8) {
            int s[8];
            #pragma unroll
            for (int i = 0; i < 8; i++) s[i] = __shfl_sync(0xffffffffu, s_l, k + i);
            float4 v[8];
            #pragma unroll
            for (int i = 0; i < 8; i++) v[i] = in[s[i] * ROW4 + lane];
            #pragma unroll
            for (int i = 0; i < 8; i++) {
                acc.x += v[i].x; acc.y += v[i].y; acc.z += v[i].z; acc.w += v[i].w;
            }
        }
        for (; k < cnt; k++) {
            int s = __shfl_sync(0xffffffffu, s_l, k);
            float4 v = in[s * ROW4 + lane];
            acc.x += v.x; acc.y += v.y; acc.z += v.z; acc.w += v.w;
        }
    }
    float nn = g_norm[w];
    acc.x *= nn; acc.y *= nn; acc.z *= nn; acc.w *= nn;
    g_bufA[w * ROW4 + lane] = acc;
}

// ---------------- fused MLP: out = relu(h@W1+b1)@W2 + b2 ----------------
// TM=64 rows/CTA, 256 threads. Warp ty owns rows ty*8..+7; lane tx owns cols
// tx*8..+7 of z. GEMM1 uses fma.rn.f32x2 packed pairs; z stays in registers;
// GEMM2 shuffle-reduces against smem W2^T. Dynamic smem: sh(32KB) + union(40KB).
#define TM1 64
__global__ __launch_bounds__(256)
void k_mlp(const float4* __restrict__ W1v, const float* __restrict__ b1,
           const float* __restrict__ W2,  const float* __restrict__ b2,
           float* __restrict__ out) {
    extern __shared__ float dyn[];
    float* sh = dyn;                 // [64][128]
    float* sw = dyn + TM1 * IN_F;    // GEMM1: [16][256] W1-tile; GEMM2: [40][256] W2^T

    const int t  = threadIdx.x;
    const int tx = t & 31;
    const int ty = t >> 5;
    const int row0 = blockIdx.x * TM1;

    // load h tile: 64x128 = 2048 float4
    const float4* hv = g_bufA + row0 * ROW4;
    float4* sh4 = reinterpret_cast<float4*>(sh);
    #pragma unroll
    for (int i = 0; i < 8; i++) sh4[t + i * 256] = hv[t + i * 256];

    ull accp[8][4];
    #pragma unroll
    for (int r = 0; r < 8; r++)
        #pragma unroll
        for (int p = 0; p < 4; p++) accp[r][p] = 0ull;

    #pragma unroll 1
    for (int kt = 0; kt < 8; kt++) {
        __syncthreads();
        float4* sw4 = reinterpret_cast<float4*>(sw);
        const float4* w1t = W1v + kt * 16 * (HID / 4);   // 16 rows = 1024 float4
        #pragma unroll
        for (int i = 0; i < 4; i++) sw4[t + i * 256] = w1t[t + i * 256];
        __syncthreads();

        #pragma unroll
        for (int kk = 0; kk < 16; kk++) {
            const ulonglong2* wp =
                reinterpret_cast<const ulonglong2*>(sw + kk * HID + tx * 8);
            ulonglong2 wA = wp[0];
            ulonglong2 wB = wp[1];
            #pragma unroll
            for (int rr = 0; rr < 8; rr++) {
                float a = sh[(ty * 8 + rr) * IN_F + kt * 16 + kk];
                ull a2; PACKDUP(a2, a);
                FMA2(accp[rr][0], a2, wA.x);
                FMA2(accp[rr][1], a2, wA.y);
                FMA2(accp[rr][2], a2, wB.x);
                FMA2(accp[rr][3], a2, wB.y);
            }
        }
    }

    // bias + relu + repack z pairs
    const float4* b1v = reinterpret_cast<const float4*>(b1 + tx * 8);
    float4 bb0 = b1v[0], bb1 = b1v[1];
    float bb[8] = {bb0.x, bb0.y, bb0.z, bb0.w, bb1.x, bb1.y, bb1.z, bb1.w};

    ull zp[8][4];
    #pragma unroll
    for (int rr = 0; rr < 8; rr++) {
        #pragma unroll
        for (int p = 0; p < 4; p++) {
            float lo, hi;
            UNPACK2(lo, hi, accp[rr][p]);
            lo = fmaxf(lo + bb[2 * p],     0.f);
            hi = fmaxf(hi + bb[2 * p + 1], 0.f);
            PACK2(zp[rr][p], lo, hi);
        }
    }

    // swap union region to W2^T
    __syncthreads();
    for (int i = t; i < CLS * HID; i += 256) {
        int c = i >> 8, k = i & 255;
        sw[i] = W2[k * CLS + c];
    }
    __syncthreads();

    // GEMM2: out[r][c] = sum_k z[r][k] * W2[k][c]
    #pragma unroll 1
    for (int c = 0; c < CLS; c++) {
        const ulonglong2* wp =
            reinterpret_cast<const ulonglong2*>(sw + c * HID + tx * 8);
        ulonglong2 wA = wp[0];
        ulonglong2 wB = wp[1];
        float p[8];
        #pragma unroll
        for (int rr = 0; rr < 8; rr++) {
            ull s2 = 0ull;
            FMA2(s2, zp[rr][0], wA.x);
            FMA2(s2, zp[rr][1], wA.y);
            FMA2(s2, zp[rr][2], wB.x);
            FMA2(s2, zp[rr][3], wB.y);
            float lo, hi;
            UNPACK2(lo, hi, s2);
            p[rr] = lo + hi;
        }
        #pragma unroll
        for (int off = 16; off > 0; off >>= 1) {
            #pragma unroll
            for (int rr = 0; rr < 8; rr++)
                p[rr] += __shfl_xor_sync(0xffffffffu, p[rr], off);
        }
        if (tx == 0) {
            float bc = b2[c];
            #pragma unroll
            for (int rr = 0; rr < 8; rr++)
                out[(row0 + ty * 8 + rr) * CLS + c] = p[rr] + bc;
        }
    }
}

// ---------------- launch ----------------
extern "C" void kernel_launch(void* const* d_in, const int* in_sizes, int n_in,
                              void* d_out, int out_size) {
    const float* features = (const float*)d_in[0];
    const int*   src      = (const int*)d_in[1];
    const int*   dst      = (const int*)d_in[2];
    const float* W1       = (const float*)d_in[3];
    const float* b1       = (const float*)d_in[4];
    const float* W2       = (const float*)d_in[5];
    const float* b2       = (const float*)d_in[6];
    float* out = (float*)d_out;

    const int nodeBlocks = (N_NODES + 255) / 256;   // 157
    const int edgeBlocks = (N_EDGES + 255) / 256;   // 2500
    const int warpBlocks = N_NODES * 32 / 256;      // 5000 (exact)
    const int sortBlocks = N_NODES / 8;             // 5000 (exact, warp/node)
    const int mlpSmem    = (TM1 * IN_F + CLS * HID) * 4;   // 73728 B

    static int smem_set = 0;
    if (!smem_set) {
        cudaFuncSetAttribute(k_mlp, cudaFuncAttributeMaxDynamicSharedMemorySize,
                             mlpSmem);
        smem_set = 1;
    }

    k_zero<<<nodeBlocks, 256>>>();
    k_deg<<<edgeBlocks, 256>>>(dst);
    k_scan<<<1, 1024>>>();
    k_fill<<<edgeBlocks, 256>>>(src, dst);
    k_sort<<<sortBlocks, 256>>>();
    k_norm<<<nodeBlocks, 256>>>();

    k_gather1<<<warpBlocks, 256>>>((const float4*)features);   // hop 1 (+src norm, +norm^2)
    k_gather2<<<warpBlocks, 256>>>();                          // hop 2 (+final norm)

    k_mlp<<<N_NODES / TM1, 256, mlpSmem>>>((const float4*)W1, b1, W2, b2, out);
}

// round 5
// speedup vs baseline: 2.0658x; 1.0764x over previous
#include <cuda_runtime.h>

#define N_NODES 40000
#define N_EDGES 640000
#define IN_F    128
#define HID     256
#define CLS     40
#define ROW4    (IN_F/4)   // 32 float4 per row
#define NBLK    157        // ceil(40000/256)

typedef unsigned long long ull;

// packed f32x2 helpers (sm_103a)
#define FMA2(d, a, b)    asm("fma.rn.f32x2 %0, %1, %2, %3;" : "=l"(d) : "l"(a), "l"(b), "l"(d))
#define PACKDUP(d, f)    asm("mov.b64 %0, {%1, %1};" : "=l"(d) : "f"(f))
#define PACK2(d, lo, hi) asm("mov.b64 %0, {%1, %2};" : "=l"(d) : "f"(lo), "f"(hi))
#define UNPACK2(lo, hi, s) asm("mov.b64 {%0, %1}, %2;" : "=f"(lo), "=f"(hi) : "l"(s))

// ---- scratch (__device__ globals; no allocations allowed) ----
__device__ int    g_deg[N_NODES];
__device__ int    g_rowptr[N_NODES + 1];
__device__ int    g_cursor[N_NODES];
__device__ int    g_bsum[NBLK];
__device__ int    g_boff[NBLK];
__device__ int    g_csr[N_EDGES];
__device__ float  g_norm[N_NODES];
__device__ float4 g_bufB[N_NODES * ROW4];   // 20.48 MB (hop1 out)

// ---------------- degree ----------------
__global__ void k_deg(const int* __restrict__ dst) {
    int e = blockIdx.x * blockDim.x + threadIdx.x;
    if (e < N_EDGES) atomicAdd(&g_deg[dst[e]], 1);
}

// ---------------- 3-phase exclusive scan ----------------
// A: per-block local exclusive scan of deg -> rowptr (local), block total -> bsum
__global__ __launch_bounds__(256)
void k_scanA() {
    __shared__ int sm[256];
    const int t = threadIdx.x;
    const int i = blockIdx.x * 256 + t;
    int v = (i < N_NODES) ? g_deg[i] : 0;
    sm[t] = v;
    __syncthreads();
    int acc = v;
    for (int o = 1; o < 256; o <<= 1) {
        int u = (t >= o) ? sm[t - o] : 0;
        __syncthreads();
        acc += u;
        sm[t] = acc;
        __syncthreads();
    }
    // sm[t] = inclusive; exclusive = inclusive - v
    if (i < N_NODES) g_rowptr[i] = acc - v;
    if (t == 255) g_bsum[blockIdx.x] = acc;
}

// B: scan the 157 block totals (one block)
__global__ __launch_bounds__(256)
void k_scanB() {
    __shared__ int sm[256];
    const int t = threadIdx.x;
    int v = (t < NBLK) ? g_bsum[t] : 0;
    sm[t] = v;
    __syncthreads();
    int acc = v;
    for (int o = 1; o < 256; o <<= 1) {
        int u = (t >= o) ? sm[t - o] : 0;
        __syncthreads();
        acc += u;
        sm[t] = acc;
        __syncthreads();
    }
    if (t < NBLK) g_boff[t] = acc - v;      // exclusive block offset
    if (t == NBLK - 1) g_rowptr[N_NODES] = acc;   // total = E
}

// C: add block offsets; init cursor; compute norm
__global__ __launch_bounds__(256)
void k_scanC() {
    const int i = blockIdx.x * 256 + threadIdx.x;
    if (i < N_NODES) {
        int rp = g_rowptr[i] + g_boff[blockIdx.x];
        g_rowptr[i] = rp;
        g_cursor[i] = rp;
        g_norm[i] = rsqrtf(fmaxf((float)g_deg[i], 1.0f));
    }
}

// ---------------- CSR fill (atomic cursor; order canonicalized by sort) --------
__global__ void k_fill(const int* __restrict__ src, const int* __restrict__ dst) {
    int e = blockIdx.x * blockDim.x + threadIdx.x;
    if (e < N_EDGES) {
        int d = dst[e];
        int pos = atomicAdd(&g_cursor[d], 1);
        g_csr[pos] = src[e];
    }
}

// ---------------- per-node sort: warp bitonic (d<=32), smem fallback ----------
__global__ __launch_bounds__(256)
void k_sort() {
    __shared__ int scratch[8][512];
    const int wi   = threadIdx.x >> 5;
    const int lane = threadIdx.x & 31;
    const int n = blockIdx.x * 8 + wi;          // grid = 5000 blocks exactly
    int b = g_rowptr[n], e = g_rowptr[n + 1];
    int d = e - b;
    if (d <= 1) return;
    if (d <= 32) {
        int v = (lane < d) ? g_csr[b + lane] : 0x7fffffff;
        #pragma unroll
        for (int k = 2; k <= 32; k <<= 1) {
            #pragma unroll
            for (int j = k >> 1; j > 0; j >>= 1) {
                int pv = __shfl_xor_sync(0xffffffffu, v, j);
                bool dir   = ((lane & k) == 0);
                bool lower = ((lane & j) == 0);
                v = ((lower == dir) ? min(v, pv) : max(v, pv));
            }
        }
        if (lane < d) g_csr[b + lane] = v;
    } else if (d <= 512) {
        int* s = scratch[wi];
        for (int i = lane; i < d; i += 32) s[i] = g_csr[b + i];
        __syncwarp();
        if (lane == 0) {
            for (int i = 1; i < d; i++) {
                int v = s[i], j = i - 1;
                while (j >= 0 && s[j] > v) { s[j + 1] = s[j]; j--; }
                s[j + 1] = v;
            }
        }
        __syncwarp();
        for (int i = lane; i < d; i += 32) g_csr[b + i] = s[i];
    } else {
        if (lane == 0) {   // unreachable for this graph; correctness safety net
            for (int i = b + 1; i < e; i++) {
                int v = g_csr[i], j = i - 1;
                while (j >= b && g_csr[j] > v) { g_csr[j + 1] = g_csr[j]; j--; }
                g_csr[j + 1] = v;
            }
        }
    }
}

// ---------------- hop 1: bufB[d] = norm[d]^2 * sum_s feat[s]*norm[s] ----------
// One warp per dst node; lane owns one float4 slice. Source norm fused in.
__global__ __launch_bounds__(256)
void k_gather1(const float4* __restrict__ feat) {
    int gt = blockIdx.x * blockDim.x + threadIdx.x;
    int w = gt >> 5, lane = gt & 31;
    int beg = g_rowptr[w], end = g_rowptr[w + 1];
    float4 acc = make_float4(0.f, 0.f, 0.f, 0.f);
    for (int base = beg; base < end; base += 32) {
        int cnt = min(32, end - base);
        int idx = base + lane;
        int   s_l = (idx < end) ? g_csr[idx] : 0;
        float n_l = g_norm[s_l];
        int k = 0;
        for (; k + 8 <= cnt; k += 8) {
            int   s[8]; float nn[8];
            #pragma unroll
            for (int i = 0; i < 8; i++) {
                s[i]  = __shfl_sync(0xffffffffu, s_l, k + i);
                nn[i] = __shfl_sync(0xffffffffu, n_l, k + i);
            }
            float4 v[8];
            #pragma unroll
            for (int i = 0; i < 8; i++) v[i] = feat[s[i] * ROW4 + lane];
            #pragma unroll
            for (int i = 0; i < 8; i++) {
                acc.x = fmaf(v[i].x, nn[i], acc.x);
                acc.y = fmaf(v[i].y, nn[i], acc.y);
                acc.z = fmaf(v[i].z, nn[i], acc.z);
                acc.w = fmaf(v[i].w, nn[i], acc.w);
            }
        }
        for (; k < cnt; k++) {
            int   s  = __shfl_sync(0xffffffffu, s_l, k);
            float nn = __shfl_sync(0xffffffffu, n_l, k);
            float4 v = feat[s * ROW4 + lane];
            acc.x = fmaf(v.x, nn, acc.x);
            acc.y = fmaf(v.y, nn, acc.y);
            acc.z = fmaf(v.z, nn, acc.z);
            acc.w = fmaf(v.w, nn, acc.w);
        }
    }
    float nn = g_norm[w];
    float sc = nn * nn;
    acc.x *= sc; acc.y *= sc; acc.z *= sc; acc.w *= sc;
    g_bufB[w * ROW4 + lane] = acc;
}

// ---------------- fused hop2 + MLP ----------------
// CTA owns 64 contiguous dst rows. Phase 1: each warp gathers its 8 rows from
// bufB (hop 2, final norm) straight into the smem h-tile (warp-private rows, no
// sync needed). Phase 2: GEMM1 with fma.rn.f32x2, z in registers. Phase 3:
// GEMM2 shuffle-reduce vs smem W2^T.
#define TM1 64
__global__ __launch_bounds__(256)
void k_mlp(const float4* __restrict__ W1v, const float* __restrict__ b1,
           const float* __restrict__ W2,  const float* __restrict__ b2,
           float* __restrict__ out) {
    extern __shared__ float dyn[];
    float* sh = dyn;                 // [64][128] h tile
    float* sw = dyn + TM1 * IN_F;    // GEMM1: [16][256] W1-tile; GEMM2: [40][256] W2^T

    const int t  = threadIdx.x;
    const int tx = t & 31;           // lane
    const int ty = t >> 5;           // warp
    const int row0 = blockIdx.x * TM1;

    float4* sh4 = reinterpret_cast<float4*>(sh);

    // ---- phase 1: gather hop 2 into smem (warp ty -> rows ty*8..+7) ----
    #pragma unroll 1
    for (int rr = 0; rr < 8; rr++) {
        const int w = row0 + ty * 8 + rr;
        int beg = g_rowptr[w], end = g_rowptr[w + 1];
        float4 acc = make_float4(0.f, 0.f, 0.f, 0.f);
        for (int base = beg; base < end; base += 32) {
            int cnt = min(32, end - base);
            int idx = base + tx;
            int s_l = (idx < end) ? g_csr[idx] : 0;
            int k = 0;
            for (; k + 8 <= cnt; k += 8) {
                int s[8];
                #pragma unroll
                for (int i = 0; i < 8; i++) s[i] = __shfl_sync(0xffffffffu, s_l, k + i);
                float4 v[8];
                #pragma unroll
                for (int i = 0; i < 8; i++) v[i] = g_bufB[s[i] * ROW4 + tx];
                #pragma unroll
                for (int i = 0; i < 8; i++) {
                    acc.x += v[i].x; acc.y += v[i].y; acc.z += v[i].z; acc.w += v[i].w;
                }
            }
            for (; k < cnt; k++) {
                int s = __shfl_sync(0xffffffffu, s_l, k);
                float4 v = g_bufB[s * ROW4 + tx];
                acc.x += v.x; acc.y += v.y; acc.z += v.z; acc.w += v.w;
            }
        }
        float nn = g_norm[w];
        acc.x *= nn; acc.y *= nn; acc.z *= nn; acc.w *= nn;
        sh4[(ty * 8 + rr) * ROW4 + tx] = acc;
    }

    // ---- phase 2: GEMM1 (z = relu(h@W1+b1) in registers) ----
    ull accp[8][4];
    #pragma unroll
    for (int r = 0; r < 8; r++)
        #pragma unroll
        for (int p = 0; p < 4; p++) accp[r][p] = 0ull;

    #pragma unroll 1
    for (int kt = 0; kt < 8; kt++) {
        __syncthreads();
        float4* sw4 = reinterpret_cast<float4*>(sw);
        const float4* w1t = W1v + kt * 16 * (HID / 4);   // 16 rows = 1024 float4
        #pragma unroll
        for (int i = 0; i < 4; i++) sw4[t + i * 256] = w1t[t + i * 256];
        __syncthreads();

        #pragma unroll
        for (int k4 = 0; k4 < 4; k4++) {
            // broadcast a-values: 4 consecutive k per row as one float4
            float4 a4[8];
            #pragma unroll
            for (int rr = 0; rr < 8; rr++)
                a4[rr] = sh4[(ty * 8 + rr) * ROW4 + kt * 4 + k4];
            #pragma unroll
            for (int q = 0; q < 4; q++) {
                int kk = k4 * 4 + q;
                const ulonglong2* wp =
                    reinterpret_cast<const ulonglong2*>(sw + kk * HID + tx * 8);
                ulonglong2 wA = wp[0];
                ulonglong2 wB = wp[1];
                #pragma unroll
                for (int rr = 0; rr < 8; rr++) {
                    float a = (q == 0) ? a4[rr].x : (q == 1) ? a4[rr].y
                             : (q == 2) ? a4[rr].z : a4[rr].w;
                    ull a2; PACKDUP(a2, a);
                    FMA2(accp[rr][0], a2, wA.x);
                    FMA2(accp[rr][1], a2, wA.y);
                    FMA2(accp[rr][2], a2, wB.x);
                    FMA2(accp[rr][3], a2, wB.y);
                }
            }
        }
    }

    // bias + relu + repack z pairs
    const float4* b1v = reinterpret_cast<const float4*>(b1 + tx * 8);
    float4 bb0 = b1v[0], bb1 = b1v[1];
    float bb[8] = {bb0.x, bb0.y, bb0.z, bb0.w, bb1.x, bb1.y, bb1.z, bb1.w};

    ull zp[8][4];
    #pragma unroll
    for (int rr = 0; rr < 8; rr++) {
        #pragma unroll
        for (int p = 0; p < 4; p++) {
            float lo, hi;
            UNPACK2(lo, hi, accp[rr][p]);
            lo = fmaxf(lo + bb[2 * p],     0.f);
            hi = fmaxf(hi + bb[2 * p + 1], 0.f);
            PACK2(zp[rr][p], lo, hi);
        }
    }

    // ---- phase 3: GEMM2 (swap union region to W2^T) ----
    __syncthreads();
    for (int i = t; i < CLS * HID; i += 256) {
        int c = i >> 8, k = i & 255;
        sw[i] = W2[k * CLS + c];
    }
    __syncthreads();

    #pragma unroll 1
    for (int c = 0; c < CLS; c++) {
        const ulonglong2* wp =
            reinterpret_cast<const ulonglong2*>(sw + c * HID + tx * 8);
        ulonglong2 wA = wp[0];
        ulonglong2 wB = wp[1];
        float p[8];
        #pragma unroll
        for (int rr = 0; rr < 8; rr++) {
            ull s2 = 0ull;
            FMA2(s2, zp[rr][0], wA.x);
            FMA2(s2, zp[rr][1], wA.y);
            FMA2(s2, zp[rr][2], wB.x);
            FMA2(s2, zp[rr][3], wB.y);
            float lo, hi;
            UNPACK2(lo, hi, s2);
            p[rr] = lo + hi;
        }
        #pragma unroll
        for (int off = 16; off > 0; off >>= 1) {
            #pragma unroll
            for (int rr = 0; rr < 8; rr++)
                p[rr] += __shfl_xor_sync(0xffffffffu, p[rr], off);
        }
        if (tx == 0) {
            float bc = b2[c];
            #pragma unroll
            for (int rr = 0; rr < 8; rr++)
                out[(row0 + ty * 8 + rr) * CLS + c] = p[rr] + bc;
        }
    }
}

// ---------------- launch ----------------
extern "C" void kernel_launch(void* const* d_in, const int* in_sizes, int n_in,
                              void* d_out, int out_size) {
    const float* features = (const float*)d_in[0];
    const int*   src      = (const int*)d_in[1];
    const int*   dst      = (const int*)d_in[2];
    const float* W1       = (const float*)d_in[3];
    const float* b1       = (const float*)d_in[4];
    const float* W2       = (const float*)d_in[5];
    const float* b2       = (const float*)d_in[6];
    float* out = (float*)d_out;

    const int edgeBlocks = (N_EDGES + 255) / 256;   // 2500
    const int warpBlocks = N_NODES * 32 / 256;      // 5000 (exact)
    const int sortBlocks = N_NODES / 8;             // 5000 (exact, warp/node)
    const int mlpSmem    = (TM1 * IN_F + CLS * HID) * 4;   // 73728 B

    static int smem_set = 0;
    if (!smem_set) {
        cudaFuncSetAttribute(k_mlp, cudaFuncAttributeMaxDynamicSharedMemorySize,
                             mlpSmem);
        smem_set = 1;
    }

    void* degPtr = nullptr;
    cudaGetSymbolAddress(&degPtr, g_deg);
    cudaMemsetAsync(degPtr, 0, N_NODES * sizeof(int));

    k_deg<<<edgeBlocks, 256>>>(dst);
    k_scanA<<<NBLK, 256>>>();
    k_scanB<<<1, 256>>>();
    k_scanC<<<NBLK, 256>>>();
    k_fill<<<edgeBlocks, 256>>>(src, dst);
    k_sort<<<sortBlocks, 256>>>();

    k_gather1<<<warpBlocks, 256>>>((const float4*)features);    // hop 1
    k_mlp<<<N_NODES / TM1, 256, mlpSmem>>>((const float4*)W1, b1, W2, b2, out);
}

// round 6
// speedup vs baseline: 2.1256x; 1.0289x over previous
#include <cuda_runtime.h>
#include <cuda_fp16.h>

#define N_NODES 40000
#define N_EDGES 640000
#define IN_F    128
#define HID     256
#define CLS     40
#define ROW4    (IN_F/4)   // 32 float4 per fp32 row
#define ROWH    32         // 32 uint2 (4 halves each) per fp16 row
#define NBLK    157        // ceil(40000/256)

typedef unsigned long long ull;

// packed f32x2 helpers (sm_103a)
#define FMA2(d, a, b)    asm("fma.rn.f32x2 %0, %1, %2, %3;" : "=l"(d) : "l"(a), "l"(b), "l"(d))
#define PACKDUP(d, f)    asm("mov.b64 %0, {%1, %1};" : "=l"(d) : "f"(f))
#define PACK2(d, lo, hi) asm("mov.b64 %0, {%1, %2};" : "=l"(d) : "f"(lo), "f"(hi))
#define UNPACK2(lo, hi, s) asm("mov.b64 {%0, %1}, %2;" : "=f"(lo), "=f"(hi) : "l"(s))

__device__ __forceinline__ uint2 pack4h(float4 a) {
    __half2 lo = __floats2half2_rn(a.x, a.y);
    __half2 hi = __floats2half2_rn(a.z, a.w);
    uint2 r;
    r.x = *reinterpret_cast<unsigned*>(&lo);
    r.y = *reinterpret_cast<unsigned*>(&hi);
    return r;
}
__device__ __forceinline__ float4 unpack4h(uint2 v) {
    __half2 lo = *reinterpret_cast<__half2*>(&v.x);
    __half2 hi = *reinterpret_cast<__half2*>(&v.y);
    float2 a = __half22float2(lo);
    float2 b = __half22float2(hi);
    return make_float4(a.x, a.y, b.x, b.y);
}

// ---- scratch (__device__ globals; no allocations allowed) ----
__device__ int    g_deg[N_NODES];
__device__ int    g_rowptr[N_NODES + 1];
__device__ int    g_cursor[N_NODES];
__device__ int    g_bsum[NBLK];
__device__ int    g_boff[NBLK];
__device__ int    g_csr[N_EDGES];
__device__ float  g_norm[N_NODES];
__device__ uint2  g_featH[N_NODES * ROWH];  // 10.24 MB  feat*norm, fp16
__device__ uint2  g_bufH[N_NODES * ROWH];   // 10.24 MB  hop1 out, fp16

// ---------------- degree ----------------
__global__ void k_deg(const int* __restrict__ dst) {
    int e = blockIdx.x * blockDim.x + threadIdx.x;
    if (e < N_EDGES) atomicAdd(&g_deg[dst[e]], 1);
}

// ---------------- 3-phase exclusive scan (+norm in A) ----------------
__global__ __launch_bounds__(256)
void k_scanA() {
    __shared__ int sm[256];
    const int t = threadIdx.x;
    const int i = blockIdx.x * 256 + t;
    int v = (i < N_NODES) ? g_deg[i] : 0;
    sm[t] = v;
    __syncthreads();
    int acc = v;
    for (int o = 1; o < 256; o <<= 1) {
        int u = (t >= o) ? sm[t - o] : 0;
        __syncthreads();
        acc += u;
        sm[t] = acc;
        __syncthreads();
    }
    if (i < N_NODES) {
        g_rowptr[i] = acc - v;                     // local exclusive
        g_norm[i] = rsqrtf(fmaxf((float)v, 1.0f)); // norm only needs deg
    }
    if (t == 255) g_bsum[blockIdx.x] = acc;
}

__global__ __launch_bounds__(256)
void k_scanB() {
    __shared__ int sm[256];
    const int t = threadIdx.x;
    int v = (t < NBLK) ? g_bsum[t] : 0;
    sm[t] = v;
    __syncthreads();
    int acc = v;
    for (int o = 1; o < 256; o <<= 1) {
        int u = (t >= o) ? sm[t - o] : 0;
        __syncthreads();
        acc += u;
        sm[t] = acc;
        __syncthreads();
    }
    if (t < NBLK) g_boff[t] = acc - v;
    if (t == NBLK - 1) g_rowptr[N_NODES] = acc;   // = E
}

__global__ __launch_bounds__(256)
void k_scanC() {
    const int i = blockIdx.x * 256 + threadIdx.x;
    if (i < N_NODES) {
        int rp = g_rowptr[i] + g_boff[blockIdx.x];
        g_rowptr[i] = rp;
        g_cursor[i] = rp;
    }
}

// ---------------- prescale: featH = fp16(feat * norm) ----------------
__global__ __launch_bounds__(256)
void k_prescale(const float4* __restrict__ feat4) {
    int t = blockIdx.x * blockDim.x + threadIdx.x;   // N_NODES*32 exact
    float n = g_norm[t >> 5];
    float4 v = feat4[t];
    v.x *= n; v.y *= n; v.z *= n; v.w *= n;
    g_featH[t] = pack4h(v);
}

// ---------------- CSR fill (atomic cursor; order canonicalized by sort) --------
__global__ void k_fill(const int* __restrict__ src, const int* __restrict__ dst) {
    int e = blockIdx.x * blockDim.x + threadIdx.x;
    if (e < N_EDGES) {
        int d = dst[e];
        int pos = atomicAdd(&g_cursor[d], 1);
        g_csr[pos] = src[e];
    }
}

// ---------------- per-node sort: warp bitonic (d<=32), smem fallback ----------
__global__ __launch_bounds__(256)
void k_sort() {
    __shared__ int scratch[8][512];
    const int wi   = threadIdx.x >> 5;
    const int lane = threadIdx.x & 31;
    const int n = blockIdx.x * 8 + wi;          // grid = 5000 blocks exactly
    int b = g_rowptr[n], e = g_rowptr[n + 1];
    int d = e - b;
    if (d <= 1) return;
    if (d <= 32) {
        int v = (lane < d) ? g_csr[b + lane] : 0x7fffffff;
        #pragma unroll
        for (int k = 2; k <= 32; k <<= 1) {
            #pragma unroll
            for (int j = k >> 1; j > 0; j >>= 1) {
                int pv = __shfl_xor_sync(0xffffffffu, v, j);
                bool dir   = ((lane & k) == 0);
                bool lower = ((lane & j) == 0);
                v = ((lower == dir) ? min(v, pv) : max(v, pv));
            }
        }
        if (lane < d) g_csr[b + lane] = v;
    } else if (d <= 512) {
        int* s = scratch[wi];
        for (int i = lane; i < d; i += 32) s[i] = g_csr[b + i];
        __syncwarp();
        if (lane == 0) {
            for (int i = 1; i < d; i++) {
                int v = s[i], j = i - 1;
                while (j >= 0 && s[j] > v) { s[j + 1] = s[j]; j--; }
                s[j + 1] = v;
            }
        }
        __syncwarp();
        for (int i = lane; i < d; i += 32) g_csr[b + i] = s[i];
    } else {
        if (lane == 0) {   // unreachable for this graph; correctness safety net
            for (int i = b + 1; i < e; i++) {
                int v = g_csr[i], j = i - 1;
                while (j >= b && g_csr[j] > v) { g_csr[j + 1] = g_csr[j]; j--; }
                g_csr[j + 1] = v;
            }
        }
    }
}

// ---------------- hop 1: bufH[d] = fp16( norm[d]^2 * sum_s featH[s] ) ----------
// One warp per dst node; lane owns 4 feature cols (uint2 = 4 halves).
__global__ __launch_bounds__(256)
void k_gather1() {
    int gt = blockIdx.x * blockDim.x + threadIdx.x;
    int w = gt >> 5, lane = gt & 31;
    int beg = g_rowptr[w], end = g_rowptr[w + 1];
    float4 acc = make_float4(0.f, 0.f, 0.f, 0.f);
    for (int base = beg; base < end; base += 32) {
        int cnt = min(32, end - base);
        int idx = base + lane;
        int s_l = (idx < end) ? g_csr[idx] : 0;
        int k = 0;
        for (; k + 8 <= cnt; k += 8) {
            int s[8];
            #pragma unroll
            for (int i = 0; i < 8; i++) s[i] = __shfl_sync(0xffffffffu, s_l, k + i);
            uint2 h[8];
            #pragma unroll
            for (int i = 0; i < 8; i++) h[i] = g_featH[s[i] * ROWH + lane];
            #pragma unroll
            for (int i = 0; i < 8; i++) {
                float4 v = unpack4h(h[i]);
                acc.x += v.x; acc.y += v.y; acc.z += v.z; acc.w += v.w;
            }
        }
        for (; k < cnt; k++) {
            int s = __shfl_sync(0xffffffffu, s_l, k);
            float4 v = unpack4h(g_featH[s * ROWH + lane]);
            acc.x += v.x; acc.y += v.y; acc.z += v.z; acc.w += v.w;
        }
    }
    float nn = g_norm[w];
    float sc = nn * nn;
    acc.x *= sc; acc.y *= sc; acc.z *= sc; acc.w *= sc;
    g_bufH[w * ROWH + lane] = pack4h(acc);
}

// ---------------- fused hop2 + MLP ----------------
// CTA owns 64 contiguous dst rows. Phase 1: warps gather their 8 rows from
// bufH (fp16) into the fp32 smem h-tile. Phase 2: GEMM1 (fma.rn.f32x2, z in
// regs). Phase 3: GEMM2 shuffle-reduce vs smem W2^T.
#define TM1 64
__global__ __launch_bounds__(256)
void k_mlp(const float4* __restrict__ W1v, const float* __restrict__ b1,
           const float* __restrict__ W2,  const float* __restrict__ b2,
           float* __restrict__ out) {
    extern __shared__ float dyn[];
    float* sh = dyn;                 // [64][128] h tile
    float* sw = dyn + TM1 * IN_F;    // GEMM1: [16][256] W1-tile; GEMM2: [40][256] W2^T

    const int t  = threadIdx.x;
    const int tx = t & 31;
    const int ty = t >> 5;
    const int row0 = blockIdx.x * TM1;

    float4* sh4 = reinterpret_cast<float4*>(sh);

    // ---- phase 1: gather hop 2 into smem (warp ty -> rows ty*8..+7) ----
    #pragma unroll 1
    for (int rr = 0; rr < 8; rr++) {
        const int w = row0 + ty * 8 + rr;
        int beg = g_rowptr[w], end = g_rowptr[w + 1];
        float4 acc = make_float4(0.f, 0.f, 0.f, 0.f);
        for (int base = beg; base < end; base += 32) {
            int cnt = min(32, end - base);
            int idx = base + tx;
            int s_l = (idx < end) ? g_csr[idx] : 0;
            int k = 0;
            for (; k + 8 <= cnt; k += 8) {
                int s[8];
                #pragma unroll
                for (int i = 0; i < 8; i++) s[i] = __shfl_sync(0xffffffffu, s_l, k + i);
                uint2 h[8];
                #pragma unroll
                for (int i = 0; i < 8; i++) h[i] = g_bufH[s[i] * ROWH + tx];
                #pragma unroll
                for (int i = 0; i < 8; i++) {
                    float4 v = unpack4h(h[i]);
                    acc.x += v.x; acc.y += v.y; acc.z += v.z; acc.w += v.w;
                }
            }
            for (; k < cnt; k++) {
                int s = __shfl_sync(0xffffffffu, s_l, k);
                float4 v = unpack4h(g_bufH[s * ROWH + tx]);
                acc.x += v.x; acc.y += v.y; acc.z += v.z; acc.w += v.w;
            }
        }
        float nn = g_norm[w];
        acc.x *= nn; acc.y *= nn; acc.z *= nn; acc.w *= nn;
        sh4[(ty * 8 + rr) * ROW4 + tx] = acc;
    }

    // ---- phase 2: GEMM1 (z = relu(h@W1+b1) in registers) ----
    ull accp[8][4];
    #pragma unroll
    for (int r = 0; r < 8; r++)
        #pragma unroll
        for (int p = 0; p < 4; p++) accp[r][p] = 0ull;

    #pragma unroll 1
    for (int kt = 0; kt < 8; kt++) {
        __syncthreads();
        float4* sw4 = reinterpret_cast<float4*>(sw);
        const float4* w1t = W1v + kt * 16 * (HID / 4);   // 16 rows = 1024 float4
        #pragma unroll
        for (int i = 0; i < 4; i++) sw4[t + i * 256] = w1t[t + i * 256];
        __syncthreads();

        #pragma unroll
        for (int k4 = 0; k4 < 4; k4++) {
            float4 a4[8];
            #pragma unroll
            for (int rr = 0; rr < 8; rr++)
                a4[rr] = sh4[(ty * 8 + rr) * ROW4 + kt * 4 + k4];
            #pragma unroll
            for (int q = 0; q < 4; q++) {
                int kk = k4 * 4 + q;
                const ulonglong2* wp =
                    reinterpret_cast<const ulonglong2*>(sw + kk * HID + tx * 8);
                ulonglong2 wA = wp[0];
                ulonglong2 wB = wp[1];
                #pragma unroll
                for (int rr = 0; rr < 8; rr++) {
                    float a = (q == 0) ? a4[rr].x : (q == 1) ? a4[rr].y
                             : (q == 2) ? a4[rr].z : a4[rr].w;
                    ull a2; PACKDUP(a2, a);
                    FMA2(accp[rr][0], a2, wA.x);
                    FMA2(accp[rr][1], a2, wA.y);
                    FMA2(accp[rr][2], a2, wB.x);
                    FMA2(accp[rr][3], a2, wB.y);
                }
            }
        }
    }

    // bias + relu + repack z pairs
    const float4* b1v = reinterpret_cast<const float4*>(b1 + tx * 8);
    float4 bb0 = b1v[0], bb1 = b1v[1];
    float bb[8] = {bb0.x, bb0.y, bb0.z, bb0.w, bb1.x, bb1.y, bb1.z, bb1.w};

    ull zp[8][4];
    #pragma unroll
    for (int rr = 0; rr < 8; rr++) {
        #pragma unroll
        for (int p = 0; p < 4; p++) {
            float lo, hi;
            UNPACK2(lo, hi, accp[rr][p]);
            lo = fmaxf(lo + bb[2 * p],     0.f);
            hi = fmaxf(hi + bb[2 * p + 1], 0.f);
            PACK2(zp[rr][p], lo, hi);
        }
    }

    // ---- phase 3: GEMM2 (swap union region to W2^T) ----
    __syncthreads();
    for (int i = t; i < CLS * HID; i += 256) {
        int c = i >> 8, k = i & 255;
        sw[i] = W2[k * CLS + c];
    }
    __syncthreads();

    #pragma unroll 1
    for (int c = 0; c < CLS; c++) {
        const ulonglong2* wp =
            reinterpret_cast<const ulonglong2*>(sw + c * HID + tx * 8);
        ulonglong2 wA = wp[0];
        ulonglong2 wB = wp[1];
        float p[8];
        #pragma unroll
        for (int rr = 0; rr < 8; rr++) {
            ull s2 = 0ull;
            FMA2(s2, zp[rr][0], wA.x);
            FMA2(s2, zp[rr][1], wA.y);
            FMA2(s2, zp[rr][2], wB.x);
            FMA2(s2, zp[rr][3], wB.y);
            float lo, hi;
            UNPACK2(lo, hi, s2);
            p[rr] = lo + hi;
        }
        #pragma unroll
        for (int off = 16; off > 0; off >>= 1) {
            #pragma unroll
            for (int rr = 0; rr < 8; rr++)
                p[rr] += __shfl_xor_sync(0xffffffffu, p[rr], off);
        }
        if (tx == 0) {
            float bc = b2[c];
            #pragma unroll
            for (int rr = 0; rr < 8; rr++)
                out[(row0 + ty * 8 + rr) * CLS + c] = p[rr] + bc;
        }
    }
}

// ---------------- launch ----------------
extern "C" void kernel_launch(void* const* d_in, const int* in_sizes, int n_in,
                              void* d_out, int out_size) {
    const float* features = (const float*)d_in[0];
    const int*   src      = (const int*)d_in[1];
    const int*   dst      = (const int*)d_in[2];
    const float* W1       = (const float*)d_in[3];
    const float* b1       = (const float*)d_in[4];
    const float* W2       = (const float*)d_in[5];
    const float* b2       = (const float*)d_in[6];
    float* out = (float*)d_out;

    const int edgeBlocks = (N_EDGES + 255) / 256;   // 2500
    const int warpBlocks = N_NODES * 32 / 256;      // 5000 (exact)
    const int sortBlocks = N_NODES / 8;             // 5000 (exact, warp/node)
    const int mlpSmem    = (TM1 * IN_F + CLS * HID) * 4;   // 73728 B

    static int smem_set = 0;
    if (!smem_set) {
        cudaFuncSetAttribute(k_mlp, cudaFuncAttributeMaxDynamicSharedMemorySize,
                             mlpSmem);
        smem_set = 1;
    }

    void* degPtr = nullptr;
    cudaGetSymbolAddress(&degPtr, g_deg);
    cudaMemsetAsync(degPtr, 0, N_NODES * sizeof(int));

    k_deg<<<edgeBlocks, 256>>>(dst);
    k_scanA<<<NBLK, 256>>>();
    k_scanB<<<1, 256>>>();
    k_scanC<<<NBLK, 256>>>();
    k_prescale<<<warpBlocks, 256>>>((const float4*)features);
    k_fill<<<edgeBlocks, 256>>>(src, dst);
    k_sort<<<sortBlocks, 256>>>();

    k_gather1<<<warpBlocks, 256>>>();                           // hop 1
    k_mlp<<<N_NODES / TM1, 256, mlpSmem>>>((const float4*)W1, b1, W2, b2, out);
}

// round 8
// speedup vs baseline: 3.1914x; 1.5014x over previous
#include <cuda_runtime.h>
#include <cuda_fp16.h>
#include <cstdint>

#define N_NODES 40000
#define N_EDGES 640000
#define IN_F    128
#define HID     256
#define CLS     40
#define ROW4    (IN_F/4)
#define ROWH    32
#define NBLK    157

typedef unsigned long long ull;

// packed f32x2 helpers
#define FMA2(d, a, b)    asm("fma.rn.f32x2 %0, %1, %2, %3;" : "=l"(d) : "l"(a), "l"(b), "l"(d))
#define UNPACK2(lo, hi, s) asm("mov.b64 {%0, %1}, %2;" : "=f"(lo), "=f"(hi) : "l"(s))

__device__ __forceinline__ uint2 pack4h(float4 a) {
    __half2 lo = __floats2half2_rn(a.x, a.y);
    __half2 hi = __floats2half2_rn(a.z, a.w);
    uint2 r;
    r.x = *reinterpret_cast<unsigned*>(&lo);
    r.y = *reinterpret_cast<unsigned*>(&hi);
    return r;
}
__device__ __forceinline__ float4 unpack4h(uint2 v) {
    __half2 lo = *reinterpret_cast<__half2*>(&v.x);
    __half2 hi = *reinterpret_cast<__half2*>(&v.y);
    float2 a = __half22float2(lo);
    float2 b = __half22float2(hi);
    return make_float4(a.x, a.y, b.x, b.y);
}

// ---- scratch ----
__device__ int    g_deg[N_NODES];
__device__ int    g_rowptr[N_NODES + 1];
__device__ int    g_cursor[N_NODES];
__device__ int    g_bsum[NBLK];
__device__ int    g_boff[NBLK];
__device__ int    g_csr[N_EDGES];
__device__ float  g_norm[N_NODES];
__device__ uint2  g_featH[N_NODES * ROWH];  // feat*norm fp16; REUSED as hop2 out
__device__ uint2  g_bufH[N_NODES * ROWH];   // hop1 out, fp16
__device__ __half g_W1h[HID * IN_F];        // W1^T fp16: [n][k], 64KB

// ================= preamble =================
__global__ void k_deg(const int* __restrict__ dst) {
    int e = blockIdx.x * blockDim.x + threadIdx.x;
    if (e < N_EDGES) atomicAdd(&g_deg[dst[e]], 1);
}

__global__ __launch_bounds__(256)
void k_scanA() {
    __shared__ int sm[256];
    const int t = threadIdx.x;
    const int i = blockIdx.x * 256 + t;
    int v = (i < N_NODES) ? g_deg[i] : 0;
    sm[t] = v;
    __syncthreads();
    int acc = v;
    for (int o = 1; o < 256; o <<= 1) {
        int u = (t >= o) ? sm[t - o] : 0;
        __syncthreads();
        acc += u;
        sm[t] = acc;
        __syncthreads();
    }
    if (i < N_NODES) {
        g_rowptr[i] = acc - v;
        g_norm[i] = rsqrtf(fmaxf((float)v, 1.0f));
    }
    if (t == 255) g_bsum[blockIdx.x] = acc;
}

__global__ __launch_bounds__(256)
void k_scanB() {
    __shared__ int sm[256];
    const int t = threadIdx.x;
    int v = (t < NBLK) ? g_bsum[t] : 0;
    sm[t] = v;
    __syncthreads();
    int acc = v;
    for (int o = 1; o < 256; o <<= 1) {
        int u = (t >= o) ? sm[t - o] : 0;
        __syncthreads();
        acc += u;
        sm[t] = acc;
        __syncthreads();
    }
    if (t < NBLK) g_boff[t] = acc - v;
    if (t == NBLK - 1) g_rowptr[N_NODES] = acc;
}

__global__ __launch_bounds__(256)
void k_scanC() {
    const int i = blockIdx.x * 256 + threadIdx.x;
    if (i < N_NODES) {
        int rp = g_rowptr[i] + g_boff[blockIdx.x];
        g_rowptr[i] = rp;
        g_cursor[i] = rp;
    }
}

__global__ __launch_bounds__(256)
void k_prescale(const float4* __restrict__ feat4) {
    int t = blockIdx.x * blockDim.x + threadIdx.x;
    float n = g_norm[t >> 5];
    float4 v = feat4[t];
    v.x *= n; v.y *= n; v.z *= n; v.w *= n;
    g_featH[t] = pack4h(v);
}

// W1^T fp16 prep: g_W1h[n*128+k] = fp16(W1[k][n])
__global__ __launch_bounds__(256)
void k_prepW(const float* __restrict__ W1) {
    int i = blockIdx.x * 256 + threadIdx.x;   // 32768
    int k = i >> 8, n = i & 255;              // coalesced read of W1[k][n]
    g_W1h[n * IN_F + k] = __float2half(W1[i]);
}

__global__ void k_fill(const int* __restrict__ src, const int* __restrict__ dst) {
    int e = blockIdx.x * blockDim.x + threadIdx.x;
    if (e < N_EDGES) {
        int d = dst[e];
        int pos = atomicAdd(&g_cursor[d], 1);
        g_csr[pos] = src[e];
    }
}

__global__ __launch_bounds__(256)
void k_sort() {
    __shared__ int scratch[8][512];
    const int wi   = threadIdx.x >> 5;
    const int lane = threadIdx.x & 31;
    const int n = blockIdx.x * 8 + wi;
    int b = g_rowptr[n], e = g_rowptr[n + 1];
    int d = e - b;
    if (d <= 1) return;
    if (d <= 32) {
        int v = (lane < d) ? g_csr[b + lane] : 0x7fffffff;
        #pragma unroll
        for (int k = 2; k <= 32; k <<= 1) {
            #pragma unroll
            for (int j = k >> 1; j > 0; j >>= 1) {
                int pv = __shfl_xor_sync(0xffffffffu, v, j);
                bool dir   = ((lane & k) == 0);
                bool lower = ((lane & j) == 0);
                v = ((lower == dir) ? min(v, pv) : max(v, pv));
            }
        }
        if (lane < d) g_csr[b + lane] = v;
    } else if (d <= 512) {
        int* s = scratch[wi];
        for (int i = lane; i < d; i += 32) s[i] = g_csr[b + i];
        __syncwarp();
        if (lane == 0) {
            for (int i = 1; i < d; i++) {
                int v = s[i], j = i - 1;
                while (j >= 0 && s[j] > v) { s[j + 1] = s[j]; j--; }
                s[j + 1] = v;
            }
        }
        __syncwarp();
        for (int i = lane; i < d; i += 32) g_csr[b + i] = s[i];
    } else {
        if (lane == 0) {
            for (int i = b + 1; i < e; i++) {
                int v = g_csr[i], j = i - 1;
                while (j >= b && g_csr[j] > v) { g_csr[j + 1] = g_csr[j]; j--; }
                g_csr[j + 1] = v;
            }
        }
    }
}

// ================= gathers =================
__global__ __launch_bounds__(256)
void k_gather1() {
    int gt = blockIdx.x * blockDim.x + threadIdx.x;
    int w = gt >> 5, lane = gt & 31;
    int beg = g_rowptr[w], end = g_rowptr[w + 1];
    float4 acc = make_float4(0.f, 0.f, 0.f, 0.f);
    for (int base = beg; base < end; base += 32) {
        int cnt = min(32, end - base);
        int idx = base + lane;
        int s_l = (idx < end) ? g_csr[idx] : 0;
        int k = 0;
        for (; k + 8 <= cnt; k += 8) {
            int s[8];
            #pragma unroll
            for (int i = 0; i < 8; i++) s[i] = __shfl_sync(0xffffffffu, s_l, k + i);
            uint2 h[8];
            #pragma unroll
            for (int i = 0; i < 8; i++) h[i] = g_featH[s[i] * ROWH + lane];
            #pragma unroll
            for (int i = 0; i < 8; i++) {
                float4 v = unpack4h(h[i]);
                acc.x += v.x; acc.y += v.y; acc.z += v.z; acc.w += v.w;
            }
        }
        for (; k < cnt; k++) {
            int s = __shfl_sync(0xffffffffu, s_l, k);
            float4 v = unpack4h(g_featH[s * ROWH + lane]);
            acc.x += v.x; acc.y += v.y; acc.z += v.z; acc.w += v.w;
        }
    }
    float nn = g_norm[w];
    float sc = nn * nn;
    acc.x *= sc; acc.y *= sc; acc.z *= sc; acc.w *= sc;
    g_bufH[w * ROWH + lane] = pack4h(acc);
}

// hop2: reads g_bufH, writes fp16 h into g_featH (dead after gather1)
__global__ __launch_bounds__(256)
void k_gather2() {
    int gt = blockIdx.x * blockDim.x + threadIdx.x;
    int w = gt >> 5, lane = gt & 31;
    int beg = g_rowptr[w], end = g_rowptr[w + 1];
    float4 acc = make_float4(0.f, 0.f, 0.f, 0.f);
    for (int base = beg; base < end; base += 32) {
        int cnt = min(32, end - base);
        int idx = base + lane;
        int s_l = (idx < end) ? g_csr[idx] : 0;
        int k = 0;
        for (; k + 8 <= cnt; k += 8) {
            int s[8];
            #pragma unroll
            for (int i = 0; i < 8; i++) s[i] = __shfl_sync(0xffffffffu, s_l, k + i);
            uint2 h[8];
            #pragma unroll
            for (int i = 0; i < 8; i++) h[i] = g_bufH[s[i] * ROWH + lane];
            #pragma unroll
            for (int i = 0; i < 8; i++) {
                float4 v = unpack4h(h[i]);
                acc.x += v.x; acc.y += v.y; acc.z += v.z; acc.w += v.w;
            }
        }
        for (; k < cnt; k++) {
            int s = __shfl_sync(0xffffffffu, s_l, k);
            float4 v = unpack4h(g_bufH[s * ROWH + lane]);
            acc.x += v.x; acc.y += v.y; acc.z += v.z; acc.w += v.w;
        }
    }
    float nn = g_norm[w];
    acc.x *= nn; acc.y *= nn; acc.z *= nn; acc.w *= nn;
    g_featH[w * ROWH + lane] = pack4h(acc);
}

// ================= MLP via mma.sync (HMMA) =================
// CTA = 64 rows, 256 threads (8 warps). Warp w: rows (w&3)*16..+15, cols (w>>2)*128..+127.
// smem layout (bytes):
//   hA  fp16 [64][136]  : 0      .. 17408
//   reg2                : 17408  .. 87040   (W1T fp16 [256][136] = 69632; later z fp32 [64][264] = 67584)
//   W2T fp32 [40][256]  : 87040  .. 128000
//   b1  fp32 [256]      : 128000 .. 129024
#define HPAD 68            // uint words per fp16 row (136 halves)
#define ZSTR 264
#define MLP_SMEM 129024
__global__ __launch_bounds__(256)
void k_mlp(const float* __restrict__ b1, const float* __restrict__ W2,
           const float* __restrict__ b2, float* __restrict__ out) {
    extern __shared__ __align__(16) char dyn[];
    unsigned* smHA  = reinterpret_cast<unsigned*>(dyn);
    unsigned* smW1  = reinterpret_cast<unsigned*>(dyn + 17408);
    float*    smZ   = reinterpret_cast<float*>(dyn + 17408);
    float*    smW2  = reinterpret_cast<float*>(dyn + 87040);
    float*    smB1  = reinterpret_cast<float*>(dyn + 128000);

    const int t    = threadIdx.x;
    const int wid  = t >> 5;
    const int lane = t & 31;
    const int row0 = blockIdx.x * 64;

    // ---- load h tile (fp16, hop2 out): 4096 uints ----
    const unsigned* srcH = reinterpret_cast<const unsigned*>(g_featH) + row0 * 64;
    #pragma unroll
    for (int it = 0; it < 16; it++) {
        int idx = it * 256 + t;
        int r = idx >> 6, c = idx & 63;
        smHA[r * HPAD + c] = srcH[idx];
    }
    // ---- load W1T (fp16): 4096 uint4 ----
    {
        const uint4* srcW = reinterpret_cast<const uint4*>(g_W1h);
        uint4* dstW = reinterpret_cast<uint4*>(smW1);
        #pragma unroll
        for (int it = 0; it < 16; it++) {
            int idx = it * 256 + t;
            int r = idx >> 4, q = idx & 15;
            dstW[r * 17 + q] = srcW[idx];   // 17 uint4 = 68 uints per row
        }
    }
    smB1[t] = b1[t];
    __syncthreads();

    // ---- GEMM1: 8 k-steps x 16 n8-tiles of m16n8k16 ----
    const int mrow0 = (wid & 3) * 16;
    const int ncol0 = (wid >> 2) * 128;
    const int g  = lane >> 2;
    const int ct = lane & 3;

    float acc[16][4];
    #pragma unroll
    for (int nt = 0; nt < 16; nt++)
        #pragma unroll
        for (int q = 0; q < 4; q++) acc[nt][q] = 0.f;

    #pragma unroll
    for (int kt = 0; kt < 8; kt++) {
        const int kw = kt * 8 + ct;
        unsigned a0 = smHA[(mrow0 + g) * HPAD + kw];
        unsigned a1 = smHA[(mrow0 + g + 8) * HPAD + kw];
        unsigned a2 = smHA[(mrow0 + g) * HPAD + kw + 4];
        unsigned a3 = smHA[(mrow0 + g + 8) * HPAD + kw + 4];
        #pragma unroll
        for (int nt = 0; nt < 16; nt++) {
            const int n = ncol0 + nt * 8 + g;
            unsigned b0 = smW1[n * HPAD + kw];
            unsigned b1r = smW1[n * HPAD + kw + 4];
            asm volatile(
                "mma.sync.aligned.m16n8k16.row.col.f32.f16.f16.f32 "
                "{%0,%1,%2,%3}, {%4,%5,%6,%7}, {%8,%9}, {%0,%1,%2,%3};"
                : "+f"(acc[nt][0]), "+f"(acc[nt][1]), "+f"(acc[nt][2]), "+f"(acc[nt][3])
                : "r"(a0), "r"(a1), "r"(a2), "r"(a3), "r"(b0), "r"(b1r));
        }
    }

    // ---- load W2^T while accs settle ----
    for (int i = t; i < CLS * HID; i += 256) {
        int c = i >> 8, k = i & 255;
        smW2[c * HID + k] = W2[k * CLS + c];
    }

    // ---- bias + relu + z to smem (reg2; W1T dead) ----
    __syncthreads();
    #pragma unroll
    for (int nt = 0; nt < 16; nt++) {
        const int col = ncol0 + nt * 8 + ct * 2;
        float bi0 = smB1[col], bi1 = smB1[col + 1];
        float2 z0, z1;
        z0.x = fmaxf(acc[nt][0] + bi0, 0.f);
        z0.y = fmaxf(acc[nt][1] + bi1, 0.f);
        z1.x = fmaxf(acc[nt][2] + bi0, 0.f);
        z1.y = fmaxf(acc[nt][3] + bi1, 0.f);
        *reinterpret_cast<float2*>(smZ + (mrow0 + g) * ZSTR + col)     = z0;
        *reinterpret_cast<float2*>(smZ + (mrow0 + g + 8) * ZSTR + col) = z1;
    }
    __syncthreads();

    // ---- GEMM2: out = z @ W2 + b2 (warp wid -> rows wid*8..+7) ----
    const int rbase = wid * 8;
    ull zp[8][4];
    #pragma unroll
    for (int rr = 0; rr < 8; rr++) {
        const ulonglong2* zr =
            reinterpret_cast<const ulonglong2*>(smZ + (rbase + rr) * ZSTR + lane * 8);
        ulonglong2 a = zr[0], b = zr[1];
        zp[rr][0] = a.x; zp[rr][1] = a.y; zp[rr][2] = b.x; zp[rr][3] = b.y;
    }
    #pragma unroll 1
    for (int c = 0; c < CLS; c++) {
        const ulonglong2* wp =
            reinterpret_cast<const ulonglong2*>(smW2 + c * HID + lane * 8);
        ulonglong2 wA = wp[0], wB = wp[1];
        float p[8];
        #pragma unroll
        for (int rr = 0; rr < 8; rr++) {
            ull s2 = 0ull;
            FMA2(s2, zp[rr][0], wA.x);
            FMA2(s2, zp[rr][1], wA.y);
            FMA2(s2, zp[rr][2], wB.x);
            FMA2(s2, zp[rr][3], wB.y);
            float lo, hi;
            UNPACK2(lo, hi, s2);
            p[rr] = lo + hi;
        }
        #pragma unroll
        for (int off = 16; off > 0; off >>= 1) {
            #pragma unroll
            for (int rr = 0; rr < 8; rr++)
                p[rr] += __shfl_xor_sync(0xffffffffu, p[rr], off);
        }
        if (lane == 0) {
            float bc = b2[c];
            #pragma unroll
            for (int rr = 0; rr < 8; rr++)
                out[(row0 + rbase + rr) * CLS + c] = p[rr] + bc;
        }
    }
}

// ================= launch =================
extern "C" void kernel_launch(void* const* d_in, const int* in_sizes, int n_in,
                              void* d_out, int out_size) {
    const float* features = (const float*)d_in[0];
    const int*   src      = (const int*)d_in[1];
    const int*   dst      = (const int*)d_in[2];
    const float* W1       = (const float*)d_in[3];
    const float* b1       = (const float*)d_in[4];
    const float* W2       = (const float*)d_in[5];
    const float* b2       = (const float*)d_in[6];
    float* out = (float*)d_out;

    const int edgeBlocks = (N_EDGES + 255) / 256;   // 2500
    const int warpBlocks = N_NODES * 32 / 256;      // 5000
    const int sortBlocks = N_NODES / 8;             // 5000
    const int mlpBlocks  = N_NODES / 64;            // 625

    static int init_done = 0;
    if (!init_done) {
        cudaFuncSetAttribute(k_mlp, cudaFuncAttributeMaxDynamicSharedMemorySize,
                             MLP_SMEM);
        init_done = 1;
    }

    void* degPtr = nullptr;
    cudaGetSymbolAddress(&degPtr, g_deg);
    cudaMemsetAsync(degPtr, 0, N_NODES * sizeof(int));

    k_prepW<<<128, 256>>>(W1);
    k_deg<<<edgeBlocks, 256>>>(dst);
    k_scanA<<<NBLK, 256>>>();
    k_scanB<<<1, 256>>>();
    k_scanC<<<NBLK, 256>>>();
    k_prescale<<<warpBlocks, 256>>>((const float4*)features);
    k_fill<<<edgeBlocks, 256>>>(src, dst);
    k_sort<<<sortBlocks, 256>>>();

    k_gather1<<<warpBlocks, 256>>>();
    k_gather2<<<warpBlocks, 256>>>();

    k_mlp<<<mlpBlocks, 256, MLP_SMEM>>>(b1, W2, b2, out);
}